// round 14
// baseline (speedup 1.0000x reference)
#include <cuda_runtime.h>

// Problem constants (fixed by reference: (3,x)-regular-column LDPC)
#define N_VAR  1152
#define M_CHK  576
#define E_EDGE 3456   // N_VAR * 3
#define E_STRIDE 3464 // lrk row stride; [E_EDGE, E_STRIDE) = zero pad slots
#define BATCH  16
#define MAXD   32     // max co-check neighbors per edge (padded count <= MAXD)
#define MAX_IT 8      // provisioned launches; guarded by device-read bp_iter_num
#define STEP_T 384    // threads per step block (384 | 3456; whole variables)

// Scratch (no allocation) — re-derived every launch (graph-replay safe).
// NOTE: g_lrk slots [b*E_STRIDE + E_EDGE, b*E_STRIDE + E_STRIDE) are NEVER
// written; __device__ globals are zero-initialized => permanent exact zeros
// used as gather padding.
__device__ int    g_p_r2l[E_EDGE];            // col-major edge -> row-major index
__device__ int    g_p_l2r[E_EDGE];            // inverse permutation
__device__ int    g_adj[E_EDGE * MAXD];       // padded adjacency (ascending + sentinels)
__device__ int    g_ndeg[E_EDGE];             // padded neighbor count (multiple of 8)
__device__ int    g_sel_y;                    // 1 if en1 is H_xe_v_sumc_to_y
__device__ float2 g_lrk[BATCH * E_STRIDE];    // per col-major edge: {log-mag, k-sign}

// ---------------------------------------------------------------------------
// Kernel 1: classify the two [E*N] inputs. H_x_to_xe0[e, e/3]==1 for ALL e.
// ---------------------------------------------------------------------------
__global__ void probe_en_kernel(const float* __restrict__ en0,
                                const float* __restrict__ en1) {
    __shared__ int w0[32], w1[32];
    int tid = threadIdx.x;
    int c0 = 0, c1 = 0;
    for (int e = tid; e < E_EDGE; e += 1024) {
        size_t off = (size_t)e * N_VAR + e / 3;
        c0 += (en0[off] == 1.0f) ? 1 : 0;
        c1 += (en1[off] == 1.0f) ? 1 : 0;
    }
    for (int o = 16; o > 0; o >>= 1) {
        c0 += __shfl_down_sync(0xffffffff, c0, o);
        c1 += __shfl_down_sync(0xffffffff, c1, o);
    }
    if ((tid & 31) == 0) { w0[tid >> 5] = c0; w1[tid >> 5] = c1; }
    __syncthreads();
    if (tid == 0) {
        int t0 = 0, t1 = 0;
        for (int w = 0; w < 32; ++w) { t0 += w0[w]; t1 += w1[w]; }
        g_sel_y = (t1 == E_EDGE && t0 != E_EDGE) ? 0 : 1;   // other one is Hy
    }
}

// ---------------------------------------------------------------------------
// Kernel 2: extract p_r2l / p_l2r from H_xe_v_sumc_to_y [N_VAR, E].
// Row v has exactly 3 ones at ascending columns = p_r2l[3v..3v+2].
// ---------------------------------------------------------------------------
__global__ void extract_perm_kernel(const float* __restrict__ en0,
                                    const float* __restrict__ en1) {
    const float* Hy = g_sel_y ? en1 : en0;
    int v = blockIdx.x;
    __shared__ int idxs[8];
    __shared__ int cnt;
    if (threadIdx.x == 0) { cnt = 0; idxs[0] = 0; idxs[1] = 0; idxs[2] = 0; }
    __syncthreads();

    const float4* row = reinterpret_cast<const float4*>(Hy + (size_t)v * E_EDGE);
    for (int q = threadIdx.x; q < E_EDGE / 4; q += blockDim.x) {
        float4 f = row[q];
        if (f.x != 0.0f) { int p = atomicAdd(&cnt, 1); if (p < 8) idxs[p] = 4 * q + 0; }
        if (f.y != 0.0f) { int p = atomicAdd(&cnt, 1); if (p < 8) idxs[p] = 4 * q + 1; }
        if (f.z != 0.0f) { int p = atomicAdd(&cnt, 1); if (p < 8) idxs[p] = 4 * q + 2; }
        if (f.w != 0.0f) { int p = atomicAdd(&cnt, 1); if (p < 8) idxs[p] = 4 * q + 3; }
    }
    __syncthreads();
    if (threadIdx.x == 0) {
        int a = idxs[0], b = idxs[1], c = idxs[2], t;
        if (a > b) { t = a; a = b; b = t; }
        if (b > c) { t = b; b = c; c = t; }
        if (a > b) { t = a; a = b; b = t; }
        g_p_r2l[3 * v + 0] = a;  g_p_l2r[a] = 3 * v + 0;
        g_p_r2l[3 * v + 1] = b;  g_p_l2r[b] = 3 * v + 1;
        g_p_r2l[3 * v + 2] = c;  g_p_l2r[c] = 3 * v + 2;
    }
}

// ---------------------------------------------------------------------------
// Kernel 3: check groups + adjacency via E probes (production-validated):
// np.nonzero is row-major => a check's edges are CONTIGUOUS row-major.
// H_sumC_to_V[j-1, p_l2r[j]] != 0  <=>  edge j-1 and j share a check.
// Emits ascending adjacency PADDED to a multiple of 8 with sentinel E_EDGE
// (points at permanent-zero lrk slots => pads add exact 0.0 to the sums).
// ---------------------------------------------------------------------------
__global__ void build_groups_kernel(const float* __restrict__ ee0,
                                    const float* __restrict__ ee1) {
    __shared__ unsigned char f0[E_EDGE], f1[E_EDGE];
    __shared__ int tsum[1024];
    __shared__ int cs[M_CHK + 1];
    __shared__ int w0[32], w1[32];
    __shared__ int sel_c2v, ngroups;
    int tid = threadIdx.x;

    int c0 = 0, c1 = 0;
    for (int j = tid; j < E_EDGE; j += 1024) {
        int p0 = 0, p1 = 0;
        if (j > 0) {
            size_t off = (size_t)(j - 1) * E_EDGE + g_p_l2r[j];
            p0 = (ee0[off] != 0.0f) ? 1 : 0;
            p1 = (ee1[off] != 0.0f) ? 1 : 0;
        }
        f0[j] = (unsigned char)p0;
        f1[j] = (unsigned char)p1;
        c0 += p0; c1 += p1;
    }
    for (int o = 16; o > 0; o >>= 1) {
        c0 += __shfl_down_sync(0xffffffff, c0, o);
        c1 += __shfl_down_sync(0xffffffff, c1, o);
    }
    if ((tid & 31) == 0) { w0[tid >> 5] = c0; w1[tid >> 5] = c1; }
    __syncthreads();
    if (tid == 0) {
        int t0 = 0, t1 = 0;
        for (int w = 0; w < 32; ++w) { t0 += w0[w]; t1 += w1[w]; }
        sel_c2v = (t1 > t0) ? 1 : 0;
    }
    __syncthreads();
    const unsigned char* f = sel_c2v ? f1 : f0;

    // prefix scan of "new group" flags (4 per thread)
    int base = tid * 4;
    int loc[4], s = 0;
    #pragma unroll
    for (int m = 0; m < 4; ++m) {
        int j = base + m;
        int v = 0;
        if (j < E_EDGE) v = (j == 0) ? 1 : (f[j] ? 0 : 1);
        loc[m] = v; s += v;
    }
    tsum[tid] = s;
    __syncthreads();
    for (int off = 1; off < 1024; off <<= 1) {
        int add = (tid >= off) ? tsum[tid - off] : 0;
        __syncthreads();
        tsum[tid] += add;
        __syncthreads();
    }
    int run = (tid == 0) ? 0 : tsum[tid - 1];

    if (tid <= M_CHK) cs[tid] = E_EDGE;
    __syncthreads();
    #pragma unroll
    for (int m = 0; m < 4; ++m) {
        int j = base + m;
        if (j < E_EDGE && loc[m]) {
            if (run <= M_CHK) cs[run] = j;
            ++run;
        }
    }
    if (tid == 0) {
        int n = tsum[1023];
        ngroups = (n > M_CHK) ? M_CHK : n;
    }
    __syncthreads();

    // per group: ascending member list; per-member padded adjacency minus self
    for (int g = tid; g < ngroups; g += 1024) {
        int s0 = cs[g], e0 = cs[g + 1];
        int d = e0 - s0;
        if (d > MAXD) d = MAXD;
        int cols[MAXD];
        for (int i = 0; i < d; ++i) cols[i] = g_p_l2r[s0 + i];
        for (int i = 1; i < d; ++i) {
            int key = cols[i], q = i - 1;
            while (q >= 0 && cols[q] > key) { cols[q + 1] = cols[q]; --q; }
            cols[q + 1] = key;
        }
        for (int i = 0; i < d; ++i) {
            int j = s0 + i;
            int own = g_p_l2r[j];
            int dexc = d - 1;
            int npad = (dexc + 7) & ~7;          // multiple of 8
            if (npad > MAXD) npad = MAXD;
            g_ndeg[j] = npad;
            int* dst = g_adj + (size_t)j * MAXD;
            int w = 0;
            for (int q = 0; q < d; ++q)
                if (cols[q] != own) dst[w++] = cols[q];
            for (; w < npad; ++w) dst[w] = E_EDGE;   // sentinel -> zero lrk slot
        }
    }
}

// ---------------------------------------------------------------------------
// Helpers (identical arithmetic to the passing R10/R13 kernels)
// ---------------------------------------------------------------------------
__device__ __forceinline__ float2 lrk_of(float x) {
    float t = tanhf(0.5f * x);
    float lr = logf(1e-8f + fabsf(t));
    float k = (x < 0.0f) ? 2.0f : ((x > 0.0f) ? 0.0f : 1.0f);
    return make_float2(lr, k);
}

// ---------------------------------------------------------------------------
// Kernel 4 (x MAX_IT): one launch per BP iteration, one THREAD PER EDGE.
// Gather unrolled in chunks of 8 independent loads (MLP=8); pads contribute
// exact +0.0 at the tail of the ascending sums => bit-identical results.
// ---------------------------------------------------------------------------
__global__ void __launch_bounds__(STEP_T)
bp_step_kernel(const float* __restrict__ llr,
               const int* __restrict__ iters_p,
               float* __restrict__ out, int it) {
    int iters = iters_p ? iters_p[0] : MAX_IT;
    if (iters < 1 || iters > MAX_IT) iters = MAX_IT;
    if (it >= iters) return;
    const bool first = (it == 0);
    const bool last  = (it == iters - 1);

    __shared__ float sm[STEP_T];

    int idx = blockIdx.x * STEP_T + threadIdx.x;   // (b, c) edge, col-major
    int b = idx / E_EDGE, c = idx - b * E_EDGE;
    const float* llrb = llr + b * N_VAR;
    const float2* lrk = g_lrk + (size_t)b * E_STRIDE;

    // ---- 1) vsr of row-major edge j = p_r2l[c]: chunked-8 gather ----
    int j = g_p_r2l[c];
    int npad = g_ndeg[j];
    const int* ad = g_adj + (size_t)j * MAXD;
    float slr = 0.0f, skf = 0.0f;
    for (int i = 0; i < npad; i += 8) {
        float2 lk[8];
        #pragma unroll
        for (int q = 0; q < 8; ++q) {
            int e = ad[i + q];
            if (first) {
                lk[q] = (e < E_EDGE) ? lrk_of(__ldg(&llrb[e / 3]))
                                     : make_float2(0.0f, 0.0f);
            } else {
                lk[q] = lrk[e];        // sentinel hits permanent-zero slot
            }
        }
        #pragma unroll
        for (int q = 0; q < 8; ++q) {  // strictly sequential, ascending order
            slr += lk[q].x;
            skf += lk[q].y;
        }
    }
    int sk = (int)skf;   // exact small integer
    // cos(sk*pi/2): exactly +-1 for even sk, 0 for odd
    float cv = (sk & 1) ? 0.0f : ((sk & 2) ? -1.0f : 1.0f);
    float prod = expf(slr) * cv;
    float sg = (prod > 0.0f) ? 1.0f : ((prod < 0.0f) ? -1.0f : 0.0f);
    float pd = prod - 2e-7f * sg;
    float vs = logf((1.0f + pd) / (1.0f - pd + 1e-10f));

    // ---- 2) sibling exchange (siblings 3v..3v+2 contiguous in block) ----
    sm[threadIdx.x] = vs;
    __syncthreads();

    int v = c / 3, r = c - 3 * v;
    int tl = threadIdx.x - r;        // threadIdx of sibling r=0
    float L = __ldg(&llrb[v]);

    if (last) {
        if (r == 0) {
            float T = (sm[tl] + sm[tl + 1]) + sm[tl + 2];   // R10 decision order
            float l = L + T;
            int sgn = (l > 0.0f) ? 1 : ((l < 0.0f) ? -1 : 0);
            out[b * N_VAR + v] = (float)((1 - sgn) >> 1);   // 0.0f / 1.0f (float!)
        }
    } else {
        // R10 v2c pairing: x = L + (vsr[j1] + vsr[j2]), ascending siblings
        float o1 = sm[tl + ((r == 0) ? 1 : 0)];
        float o2 = sm[tl + ((r == 2) ? 1 : 2)];
        g_lrk[(size_t)b * E_STRIDE + c] = lrk_of(L + (o1 + o2));
    }
}

// ---------------------------------------------------------------------------
// Inputs identified by element count (robust to ordering):
//   18432      -> llr_in [16,1152]
//   3981312 x2 -> H_x_to_xe0 [E,N] / H_xe_v_sumc_to_y [N,E]  (probed)
//   11943936x2 -> H_sumC_to_V / H_sumV_to_C [E,E]            (probed)
//   1          -> bp_iter_num int32
// Output: float32 [16, 1152] (0.0 / 1.0)
// ---------------------------------------------------------------------------
extern "C" void kernel_launch(void* const* d_in, const int* in_sizes, int n_in,
                              void* d_out, int out_size) {
    int idx_llr = -1, idx_it = -1;
    int en[2] = {-1, -1}, ee[2] = {-1, -1};
    int nen = 0, nee = 0;
    for (int i = 0; i < n_in; ++i) {
        int s = in_sizes[i];
        if (s == BATCH * N_VAR) idx_llr = i;
        else if (s == 1) idx_it = i;
        else if (s == E_EDGE * N_VAR) { if (nen < 2) en[nen] = i; nen++; }
        else if (s == E_EDGE * E_EDGE) { if (nee < 2) ee[nee] = i; nee++; }
    }
    if (idx_llr < 0) idx_llr = 0;
    if (en[0] < 0) en[0] = 1;
    if (en[1] < 0) en[1] = 4;
    if (ee[0] < 0) ee[0] = 2;
    if (ee[1] < 0) ee[1] = 3;

    const float* llr = (const float*)d_in[idx_llr];
    const float* en0 = (const float*)d_in[en[0]];
    const float* en1 = (const float*)d_in[en[1]];
    const float* ee0 = (const float*)d_in[ee[0]];
    const float* ee1 = (const float*)d_in[ee[1]];
    const int* iters = (idx_it >= 0) ? (const int*)d_in[idx_it] : (const int*)0;
    float* out = (float*)d_out;

    probe_en_kernel<<<1, 1024>>>(en0, en1);
    extract_perm_kernel<<<N_VAR, 128>>>(en0, en1);
    build_groups_kernel<<<1, 1024>>>(ee0, ee1);

    const int GB = (BATCH * E_EDGE) / STEP_T;   // 144 blocks, one wave
    for (int it = 0; it < MAX_IT; ++it)
        bp_step_kernel<<<GB, STEP_T>>>(llr, iters, out, it);
}

// round 15
// speedup vs baseline: 1.5878x; 1.5878x over previous
#include <cuda_runtime.h>

// Problem constants (fixed by reference: (3,x)-regular-column LDPC)
#define N_VAR  1152
#define M_CHK  576
#define E_EDGE 3456   // N_VAR * 3
#define BATCH  16
#define MAXD   32     // max check degree (lane-mapped)
#define MAX_IT 8      // provisioned launches; guarded by device-read bp_iter_num

// Scratch (no allocation) — re-derived every launch (graph-replay safe).
__device__ int   g_p_r2l[E_EDGE];          // col-major edge -> row-major index
__device__ int   g_p_l2r[E_EDGE];          // inverse permutation
__device__ int   g_chk_mem[M_CHK * MAXD];  // per check: member col-major edges, ASCENDING
__device__ int   g_chk_d[M_CHK];           // check degree
__device__ int   g_sel_y;                  // 1 if en1 is H_xe_v_sumc_to_y
__device__ float g_vsr[2][BATCH * E_EDGE]; // ping-pong C->V messages, col-major index

// ---------------------------------------------------------------------------
// Kernel 1: classify the two [E*N] inputs. H_x_to_xe0[e, e/3]==1 for ALL e.
// ---------------------------------------------------------------------------
__global__ void probe_en_kernel(const float* __restrict__ en0,
                                const float* __restrict__ en1) {
    __shared__ int w0[32], w1[32];
    int tid = threadIdx.x;
    int c0 = 0, c1 = 0;
    for (int e = tid; e < E_EDGE; e += 1024) {
        size_t off = (size_t)e * N_VAR + e / 3;
        c0 += (en0[off] == 1.0f) ? 1 : 0;
        c1 += (en1[off] == 1.0f) ? 1 : 0;
    }
    for (int o = 16; o > 0; o >>= 1) {
        c0 += __shfl_down_sync(0xffffffff, c0, o);
        c1 += __shfl_down_sync(0xffffffff, c1, o);
    }
    if ((tid & 31) == 0) { w0[tid >> 5] = c0; w1[tid >> 5] = c1; }
    __syncthreads();
    if (tid == 0) {
        int t0 = 0, t1 = 0;
        for (int w = 0; w < 32; ++w) { t0 += w0[w]; t1 += w1[w]; }
        g_sel_y = (t1 == E_EDGE && t0 != E_EDGE) ? 0 : 1;   // other one is Hy
    }
}

// ---------------------------------------------------------------------------
// Kernel 2: extract p_r2l / p_l2r from H_xe_v_sumc_to_y [N_VAR, E].
// Row v has exactly 3 ones at ascending columns = p_r2l[3v..3v+2].
// ---------------------------------------------------------------------------
__global__ void extract_perm_kernel(const float* __restrict__ en0,
                                    const float* __restrict__ en1) {
    const float* Hy = g_sel_y ? en1 : en0;
    int v = blockIdx.x;
    __shared__ int idxs[8];
    __shared__ int cnt;
    if (threadIdx.x == 0) { cnt = 0; idxs[0] = 0; idxs[1] = 0; idxs[2] = 0; }
    __syncthreads();

    const float4* row = reinterpret_cast<const float4*>(Hy + (size_t)v * E_EDGE);
    for (int q = threadIdx.x; q < E_EDGE / 4; q += blockDim.x) {
        float4 f = row[q];
        if (f.x != 0.0f) { int p = atomicAdd(&cnt, 1); if (p < 8) idxs[p] = 4 * q + 0; }
        if (f.y != 0.0f) { int p = atomicAdd(&cnt, 1); if (p < 8) idxs[p] = 4 * q + 1; }
        if (f.z != 0.0f) { int p = atomicAdd(&cnt, 1); if (p < 8) idxs[p] = 4 * q + 2; }
        if (f.w != 0.0f) { int p = atomicAdd(&cnt, 1); if (p < 8) idxs[p] = 4 * q + 3; }
    }
    __syncthreads();
    if (threadIdx.x == 0) {
        int a = idxs[0], b = idxs[1], c = idxs[2], t;
        if (a > b) { t = a; a = b; b = t; }
        if (b > c) { t = b; b = c; c = t; }
        if (a > b) { t = a; a = b; b = t; }
        g_p_r2l[3 * v + 0] = a;  g_p_l2r[a] = 3 * v + 0;
        g_p_r2l[3 * v + 1] = b;  g_p_l2r[b] = 3 * v + 1;
        g_p_r2l[3 * v + 2] = c;  g_p_l2r[c] = 3 * v + 2;
    }
}

// ---------------------------------------------------------------------------
// Kernel 3: check groups via E probes (production-validated):
// np.nonzero is row-major => a check's edges are CONTIGUOUS row-major.
// H_sumC_to_V[j-1, p_l2r[j]] != 0  <=>  edge j-1 and j share a check.
// Probes also classify the EE pair. Emits per-check member lists sorted
// ascending by col-major index (the matmul accumulation order).
// ---------------------------------------------------------------------------
__global__ void build_groups_kernel(const float* __restrict__ ee0,
                                    const float* __restrict__ ee1) {
    __shared__ unsigned char f0[E_EDGE], f1[E_EDGE];
    __shared__ int tsum[1024];
    __shared__ int cs[M_CHK + 1];
    __shared__ int w0[32], w1[32];
    __shared__ int sel_c2v, ngroups;
    int tid = threadIdx.x;

    int c0 = 0, c1 = 0;
    for (int j = tid; j < E_EDGE; j += 1024) {
        int p0 = 0, p1 = 0;
        if (j > 0) {
            size_t off = (size_t)(j - 1) * E_EDGE + g_p_l2r[j];
            p0 = (ee0[off] != 0.0f) ? 1 : 0;
            p1 = (ee1[off] != 0.0f) ? 1 : 0;
        }
        f0[j] = (unsigned char)p0;
        f1[j] = (unsigned char)p1;
        c0 += p0; c1 += p1;
    }
    for (int o = 16; o > 0; o >>= 1) {
        c0 += __shfl_down_sync(0xffffffff, c0, o);
        c1 += __shfl_down_sync(0xffffffff, c1, o);
    }
    if ((tid & 31) == 0) { w0[tid >> 5] = c0; w1[tid >> 5] = c1; }
    __syncthreads();
    if (tid == 0) {
        int t0 = 0, t1 = 0;
        for (int w = 0; w < 32; ++w) { t0 += w0[w]; t1 += w1[w]; }
        sel_c2v = (t1 > t0) ? 1 : 0;
    }
    __syncthreads();
    const unsigned char* f = sel_c2v ? f1 : f0;

    // prefix scan of "new group" flags (4 per thread)
    int base = tid * 4;
    int loc[4], s = 0;
    #pragma unroll
    for (int m = 0; m < 4; ++m) {
        int j = base + m;
        int v = 0;
        if (j < E_EDGE) v = (j == 0) ? 1 : (f[j] ? 0 : 1);
        loc[m] = v; s += v;
    }
    tsum[tid] = s;
    __syncthreads();
    for (int off = 1; off < 1024; off <<= 1) {
        int add = (tid >= off) ? tsum[tid - off] : 0;
        __syncthreads();
        tsum[tid] += add;
        __syncthreads();
    }
    int run = (tid == 0) ? 0 : tsum[tid - 1];

    if (tid <= M_CHK) cs[tid] = E_EDGE;
    if (tid < M_CHK) g_chk_d[tid] = 0;
    __syncthreads();
    #pragma unroll
    for (int m = 0; m < 4; ++m) {
        int j = base + m;
        if (j < E_EDGE && loc[m]) {
            if (run <= M_CHK) cs[run] = j;
            ++run;
        }
    }
    if (tid == 0) {
        int n = tsum[1023];
        ngroups = (n > M_CHK) ? M_CHK : n;
    }
    __syncthreads();

    // per group: member col-major indices sorted ascending
    for (int g = tid; g < ngroups; g += 1024) {
        int s0 = cs[g], e0 = cs[g + 1];
        int d = e0 - s0;
        if (d > MAXD) d = MAXD;
        int cols[MAXD];
        for (int i = 0; i < d; ++i) cols[i] = g_p_l2r[s0 + i];
        for (int i = 1; i < d; ++i) {
            int key = cols[i], q = i - 1;
            while (q >= 0 && cols[q] > key) { cols[q + 1] = cols[q]; --q; }
            cols[q + 1] = key;
        }
        g_chk_d[g] = d;
        for (int i = 0; i < d; ++i) g_chk_mem[g * MAXD + i] = cols[i];
    }
}

// ---------------------------------------------------------------------------
// Helper (identical arithmetic to the passing R10/R13 kernels)
// ---------------------------------------------------------------------------
__device__ __forceinline__ float2 lrk_of(float x) {
    float t = tanhf(0.5f * x);
    float lr = logf(1e-8f + fabsf(t));
    float k = (x < 0.0f) ? 2.0f : ((x > 0.0f) ? 0.0f : 1.0f);
    return make_float2(lr, k);
}

// ---------------------------------------------------------------------------
// Kernel 4 (x MAX_IT): ONE WARP PER (batch, check). Lane i owns the check's
// i-th member edge (ascending col-major). Fuses v2c (prev vsr -> lrk, R10
// pairing) with c2v (exclude-self ascending sums via shuffle broadcast —
// bit-identical order to the sorted gather). vsr ping-pongs across launches.
// ---------------------------------------------------------------------------
__global__ void __launch_bounds__(256)
bp_check_kernel(const float* __restrict__ llr,
                const int* __restrict__ iters_p, int it) {
    int iters = iters_p ? iters_p[0] : MAX_IT;
    if (iters < 1 || iters > MAX_IT) iters = MAX_IT;
    if (it >= iters) return;

    int w = (blockIdx.x * 256 + threadIdx.x) >> 5;   // global warp id
    int lane = threadIdx.x & 31;
    int b = w / M_CHK, g = w - b * M_CHK;
    if (b >= BATCH) return;

    int d = g_chk_d[g];                               // uniform across warp
    float lkx = 0.0f, lky = 0.0f;
    int c = 0;
    if (lane < d) {
        c = g_chk_mem[g * MAXD + lane];               // col-major member edge
        int v = c / 3;
        float x = __ldg(&llr[b * N_VAR + v]);
        if (it > 0) {
            int vb = 3 * v, r = c - vb;
            int s1 = vb + ((r == 0) ? 1 : 0);         // ascending siblings
            int s2 = vb + ((r == 2) ? 1 : 2);
            const float* vp = g_vsr[(it - 1) & 1] + (size_t)b * E_EDGE;
            x = x + (vp[s1] + vp[s2]);                // R10 v2c pairing
        }
        float2 lk = lrk_of(x);
        lkx = lk.x; lky = lk.y;
    }

    // exclude-self sums, strictly ascending member order (matmul order)
    float slr = 0.0f, skf = 0.0f;
    for (int q = 0; q < d; ++q) {
        float vx = __shfl_sync(0xffffffffu, lkx, q);
        float vy = __shfl_sync(0xffffffffu, lky, q);
        if (q != lane) { slr += vx; skf += vy; }
    }

    if (lane < d) {
        int sk = (int)skf;   // exact small integer
        // cos(sk*pi/2): exactly +-1 for even sk, 0 for odd
        float cv = (sk & 1) ? 0.0f : ((sk & 2) ? -1.0f : 1.0f);
        float prod = expf(slr) * cv;
        float sg = (prod > 0.0f) ? 1.0f : ((prod < 0.0f) ? -1.0f : 0.0f);
        float pd = prod - 2e-7f * sg;
        float vs = logf((1.0f + pd) / (1.0f - pd + 1e-10f));
        g_vsr[it & 1][(size_t)b * E_EDGE + c] = vs;
    }
}

// ---------------------------------------------------------------------------
// Kernel 5: hard decision. vsr is col-major-indexed; p_r2l ascending per
// variable => (vsr[3v] + vsr[3v+1]) + vsr[3v+2] is R10's decision order.
// Output float 0/1 (dtype lesson of round 9).
// ---------------------------------------------------------------------------
__global__ void bp_decision_kernel(const float* __restrict__ llr,
                                   const int* __restrict__ iters_p,
                                   float* __restrict__ out) {
    int iters = iters_p ? iters_p[0] : MAX_IT;
    if (iters < 1 || iters > MAX_IT) iters = MAX_IT;
    int pb = (iters - 1) & 1;

    int idx = blockIdx.x * blockDim.x + threadIdx.x;
    if (idx >= BATCH * N_VAR) return;
    int b = idx / N_VAR, v = idx - b * N_VAR;
    const float* vp = g_vsr[pb] + (size_t)b * E_EDGE;
    float T = (vp[3 * v] + vp[3 * v + 1]) + vp[3 * v + 2];
    float l = __ldg(&llr[idx]) + T;
    int sgn = (l > 0.0f) ? 1 : ((l < 0.0f) ? -1 : 0);
    out[idx] = (float)((1 - sgn) >> 1);   // 0.0f / 1.0f
}

// ---------------------------------------------------------------------------
// Inputs identified by element count (robust to ordering):
//   18432      -> llr_in [16,1152]
//   3981312 x2 -> H_x_to_xe0 [E,N] / H_xe_v_sumc_to_y [N,E]  (probed)
//   11943936x2 -> H_sumC_to_V / H_sumV_to_C [E,E]            (probed)
//   1          -> bp_iter_num int32
// Output: float32 [16, 1152] (0.0 / 1.0)
// ---------------------------------------------------------------------------
extern "C" void kernel_launch(void* const* d_in, const int* in_sizes, int n_in,
                              void* d_out, int out_size) {
    int idx_llr = -1, idx_it = -1;
    int en[2] = {-1, -1}, ee[2] = {-1, -1};
    int nen = 0, nee = 0;
    for (int i = 0; i < n_in; ++i) {
        int s = in_sizes[i];
        if (s == BATCH * N_VAR) idx_llr = i;
        else if (s == 1) idx_it = i;
        else if (s == E_EDGE * N_VAR) { if (nen < 2) en[nen] = i; nen++; }
        else if (s == E_EDGE * E_EDGE) { if (nee < 2) ee[nee] = i; nee++; }
    }
    if (idx_llr < 0) idx_llr = 0;
    if (en[0] < 0) en[0] = 1;
    if (en[1] < 0) en[1] = 4;
    if (ee[0] < 0) ee[0] = 2;
    if (ee[1] < 0) ee[1] = 3;

    const float* llr = (const float*)d_in[idx_llr];
    const float* en0 = (const float*)d_in[en[0]];
    const float* en1 = (const float*)d_in[en[1]];
    const float* ee0 = (const float*)d_in[ee[0]];
    const float* ee1 = (const float*)d_in[ee[1]];
    const int* iters = (idx_it >= 0) ? (const int*)d_in[idx_it] : (const int*)0;
    float* out = (float*)d_out;

    probe_en_kernel<<<1, 1024>>>(en0, en1);
    extract_perm_kernel<<<N_VAR, 128>>>(en0, en1);
    build_groups_kernel<<<1, 1024>>>(ee0, ee1);

    const int GW = (BATCH * M_CHK * 32) / 256;   // 1152 blocks, 9216 warps
    for (int it = 0; it < MAX_IT; ++it)
        bp_check_kernel<<<GW, 256>>>(llr, iters, it);
    bp_decision_kernel<<<(BATCH * N_VAR + 255) / 256, 256>>>(llr, iters, out);
}